// round 6
// baseline (speedup 1.0000x reference)
#include <cuda_runtime.h>
#include <cuda_bf16.h>
#include <cstdint>

#define S_LEN  262144
#define NDIM   128
#define TILE   128
#define NTILES 2048
#define GRID   148

// ---------------- device scratch ----------------
__device__ float g_W[NDIM * NDIM];                          // M (fp32, for l1)
__device__ __align__(16) __nv_bfloat16 g_Bsw[NDIM * NDIM];  // B[t][k]=bf16(M[k][t]), swizzled
__device__ float g_partials[GRID];

// ---------------- smem byte offsets ----------------
#define STG   0          // fp32 staging: 128 x 512B = 65536 (single buffer)
#define PLN   65536      // bf16 A plane: 128 x 256B = 32768 (swizzled)
#define BOF   98304      // B bf16 swizzled: 32768
#define NXT   131072     // boundary rows fp32: 2 x 512
#define ROWS  132096     // rowsum[128] fp32: 512
#define RED   132608     // reduction: 256 fp32 = 1024
#define SMEM_BYTES 133632

// ---------------- helpers ----------------
__device__ __forceinline__ uint32_t smem_u32(const void* p) {
    uint32_t a;
    asm("{ .reg .u64 t; cvta.to.shared.u64 t, %1; cvt.u32.u64 %0, t; }" : "=r"(a) : "l"(p));
    return a;
}
__device__ __forceinline__ uint32_t bf2(float xh, float xl) {
    uint32_t r;
    asm("cvt.rn.bf16x2.f32 %0, %1, %2;" : "=r"(r) : "f"(xh), "f"(xl));
    return r;
}
__device__ __forceinline__ float lo_f(uint32_t p) { return __uint_as_float(p << 16); }
__device__ __forceinline__ float hi_f(uint32_t p) { return __uint_as_float(p & 0xffff0000u); }

__device__ __forceinline__ float4 lds128f(uint32_t a) {
    float4 v;
    asm volatile("ld.shared.v4.f32 {%0,%1,%2,%3}, [%4];"
                 : "=f"(v.x), "=f"(v.y), "=f"(v.z), "=f"(v.w) : "r"(a));
    return v;
}
__device__ __forceinline__ float2 lds64f(uint32_t a) {
    float2 v;
    asm volatile("ld.shared.v2.f32 {%0,%1}, [%2];" : "=f"(v.x), "=f"(v.y) : "r"(a));
    return v;
}
__device__ __forceinline__ uint2 lds64u(uint32_t a) {
    uint2 v;
    asm volatile("ld.shared.v2.b32 {%0,%1}, [%2];" : "=r"(v.x), "=r"(v.y) : "r"(a));
    return v;
}
__device__ __forceinline__ uint32_t lds32(uint32_t a) {
    uint32_t v;
    asm volatile("ld.shared.b32 %0, [%1];" : "=r"(v) : "r"(a));
    return v;
}
__device__ __forceinline__ void sts64(uint32_t a, uint64_t v) {
    asm volatile("st.shared.b64 [%0], %1;" :: "r"(a), "l"(v));
}
__device__ __forceinline__ void cpa16(uint32_t dst, const void* src) {
    asm volatile("cp.async.cg.shared.global [%0], [%1], 16;" :: "r"(dst), "l"(src));
}
__device__ __forceinline__ void cpa_commit() { asm volatile("cp.async.commit_group;" ::: "memory"); }
__device__ __forceinline__ void cpa_wait0()  { asm volatile("cp.async.wait_group 0;" ::: "memory"); }

__device__ __forceinline__ void mma_bf16(float* d, const uint32_t* a, uint32_t b0, uint32_t b1) {
    asm volatile(
        "mma.sync.aligned.m16n8k16.row.col.f32.bf16.bf16.f32 "
        "{%0,%1,%2,%3}, {%4,%5,%6,%7}, {%8,%9}, {%0,%1,%2,%3};"
        : "+f"(d[0]), "+f"(d[1]), "+f"(d[2]), "+f"(d[3])
        : "r"(a[0]), "r"(a[1]), "r"(a[2]), "r"(a[3]), "r"(b0), "r"(b1));
}
__device__ __forceinline__ float softplusf(float x) {
    const float l = __logf(1.0f + __expf(x));
    return (x > 15.0f) ? x : l;
}
// swizzled byte offset of 4-elem granule: row r, element index k (bf16 plane, 256B rows)
__device__ __forceinline__ uint32_t gsw(int r, int k) {
    return (uint32_t)(r * 256 + (((k >> 2) ^ ((r & 7) << 2)) << 3) + (k & 3) * 2);
}

// ---------------- kernel A: M = W_K^T @ W_Q ----------------
extern __shared__ float wsmem[];
__global__ void __launch_bounds__(256, 1)
compute_W_kernel(const float* __restrict__ WQ, const float* __restrict__ WK) {
    float* sWQ  = wsmem;                 // 128x128
    float* sWK8 = wsmem + NDIM * NDIM;   // 128x8
    const int tid = threadIdx.x;
    const int i0  = blockIdx.x * 8;
    {
        const float4* src = (const float4*)WQ;
        float4* dst = (float4*)sWQ;
#pragma unroll
        for (int k = tid; k < NDIM * NDIM / 4; k += 256) dst[k] = src[k];
    }
    for (int k = tid; k < NDIM * 8; k += 256) {
        const int j = k >> 3, u = k & 7;
        sWK8[k] = WK[j * NDIM + i0 + u];
    }
    __syncthreads();
    const int t  = tid & 127;
    const int ib = (tid >> 7) * 4;
    float acc[4] = {0.f, 0.f, 0.f, 0.f};
#pragma unroll 4
    for (int j = 0; j < NDIM; ++j) {
        const float wq = sWQ[j * NDIM + t];
#pragma unroll
        for (int u = 0; u < 4; ++u) acc[u] = fmaf(sWK8[j * 8 + ib + u], wq, acc[u]);
    }
#pragma unroll
    for (int u = 0; u < 4; ++u) {
        const int i = i0 + ib + u;                   // k index of B
        g_W[i * NDIM + t] = acc[u];
        *(__nv_bfloat16*)((char*)g_Bsw + gsw(t, i)) = __float2bfloat16(acc[u]);
    }
}

// ---------------- fused persistent kernel ----------------
extern __shared__ char dsm[];

__device__ __forceinline__ void issue_prefetch(const float* __restrict__ In, int tile,
                                               uint32_t sb, int slot, int tid) {
    const char* src = (const char*)(In + (size_t)tile * TILE * NDIM);
#pragma unroll
    for (int j = 0; j < 16; ++j) {
        const int idx = tid + 256 * j;           // 4096 16B chunks, plain layout
        const int r = idx >> 5, c = idx & 31;
        cpa16(sb + STG + r * 512 + c * 16, src + r * 512 + c * 16);
    }
    if (tid < 32) {
        size_t nr = (size_t)tile * TILE + TILE;
        if (nr >= S_LEN) nr = 0;                  // clamped; value masked out
        cpa16(sb + NXT + slot * 512 + tid * 16, (const char*)(In + nr * NDIM) + tid * 16);
    }
    cpa_commit();
}

// fp32 staging -> bf16 plane (swizzled) + rowsums
__device__ __forceinline__ void convert_tile(uint32_t sb, int w, int lane) {
    float* sRow = (float*)(dsm + ROWS);
    const uint32_t kxor = (uint32_t)(lane << 3);   // granule index = lane
#pragma unroll
    for (int j = 0; j < 16; ++j) {
        const int r = w + 8 * j;
        const float4 v = lds128f(sb + STG + r * 512 + lane * 16);
        float s = (v.x + v.y) + (v.z + v.w);
#pragma unroll
        for (int o = 16; o; o >>= 1) s += __shfl_xor_sync(0xffffffffu, s, o);
        if (lane == 0) sRow[r] = s;
        const uint32_t p01 = bf2(v.y, v.x);
        const uint32_t p23 = bf2(v.w, v.z);
        const uint32_t off = (uint32_t)(r * 256) + (kxor ^ (uint32_t)((r & 7) << 5));
        sts64(sb + PLN + off, ((uint64_t)p23 << 32) | p01);
    }
}

__global__ void __launch_bounds__(256)
fused_kernel(const float* __restrict__ In) {
    const uint32_t sb = smem_u32(dsm);
    const int tid  = threadIdx.x;
    const int lane = tid & 31;
    const int w    = tid >> 5;
    const int m0   = (w & 3) << 5;     // warp tile: 32m x 64n (grid 4m x 2n)
    const int n0   = (w >> 2) << 6;
    const int g    = lane >> 2;
    const int q    = lane & 3;

    // stage B (global already swizzled) -> smem
    {
        const float4* src = (const float4*)g_Bsw;
        float4* dst = (float4*)(dsm + BOF);
#pragma unroll
        for (int k = tid; k < 2048; k += 256) dst[k] = src[k];
    }

    const int rA0 = m0 + g;
    const uint32_t xk = (uint32_t)(g << 5);          // (granule ^ 4g) << 3 precomputed shift form
    uint32_t baseB[8];
#pragma unroll
    for (int nf = 0; nf < 8; ++nf)
        baseB[nf] = sb + BOF + (uint32_t)(n0 + 8 * nf + g) * 256;
    const uint32_t baseA = sb + PLN + (uint32_t)rA0 * 256;
    const float* sRow = (const float*)(dsm + ROWS);

    const int bx = blockIdx.x;
    const int nt = (NTILES - bx + GRID - 1) / GRID;

    issue_prefetch(In, bx, sb, 0, tid);

    float loss = 0.f;
    for (int i = 0; i < nt; ++i) {
        const int tile = bx + i * GRID;
        cpa_wait0();
        __syncthreads();                 // staging ready; prev epilogue done with plane
        convert_tile(sb, w, lane);
        __syncthreads();                 // plane + rowsums ready
        if (i + 1 < nt) issue_prefetch(In, bx + (i + 1) * GRID, sb, (i + 1) & 1, tid);

        float dacc[2][8][4];
#pragma unroll
        for (int mh = 0; mh < 2; ++mh)
#pragma unroll
            for (int nf = 0; nf < 8; ++nf)
#pragma unroll
                for (int j = 0; j < 4; ++j) dacc[mh][nf][j] = 0.f;

#pragma unroll
        for (int ks = 0; ks < 8; ++ks) {
            const uint32_t off = ((uint32_t)(4 * ks + q) << 3) ^ xk;
            const uint2 r0  = lds64u(baseA + off);
            const uint2 r8  = lds64u(baseA + 8 * 256 + off);
            const uint2 r16 = lds64u(baseA + 16 * 256 + off);
            const uint2 r24 = lds64u(baseA + 24 * 256 + off);
            const uint32_t a0[4] = {r0.x,  r8.x,  r0.y,  r8.y};
            const uint32_t a1[4] = {r16.x, r24.x, r16.y, r24.y};
#pragma unroll
            for (int nf = 0; nf < 8; ++nf) {
                const uint2 b = lds64u(baseB[nf] + off);
                mma_bf16(dacc[0][nf], a0, b.x, b.y);
                mma_bf16(dacc[1][nf], a1, b.x, b.y);
            }
        }

        // -------- epilogue --------
        const size_t base = (size_t)tile * TILE;
        const uint32_t nextB = sb + NXT + (uint32_t)(i & 1) * 512;
#pragma unroll
        for (int mh = 0; mh < 2; ++mh) {
            const int rA = m0 + 16 * mh + g;        // <= 119
            const int rB = rA + 8;                  // <= 127
            const float rsA = sRow[rA];
            const float rsB = sRow[rB];
            const bool vB = (base + rB) < (size_t)(S_LEN - 1);
#pragma unroll
            for (int nf = 0; nf < 8; ++nf) {
                const int col0 = n0 + 8 * nf + 2 * q;             // even
                // next-row targets from bf16 plane
                const uint32_t oa = gsw(rA + 1, col0);            // 4B-aligned (col0 even)
                const uint32_t va = lds32(sb + PLN + oa);
                const float nxa0 = lo_f(va), nxa1 = hi_f(va);
                float nxb0, nxb1;
                if (rB < TILE - 1) {
                    const uint32_t ob = gsw(rB + 1, col0);
                    const uint32_t vb = lds32(sb + PLN + ob);
                    nxb0 = lo_f(vb); nxb1 = hi_f(vb);
                } else {
                    const float2 nb = lds64f(nextB + col0 * 4);
                    nxb0 = nb.x; nxb1 = nb.y;
                }
                const float* d = dacc[mh][nf];
                const float t0 = fmaf(softplusf(d[0]), rsA, -nxa0);
                const float t1 = fmaf(softplusf(d[1]), rsA, -nxa1);
                loss = fmaf(t0, t0, loss);
                loss = fmaf(t1, t1, loss);
                if (vB) {
                    const float t2 = fmaf(softplusf(d[2]), rsB, -nxb0);
                    const float t3 = fmaf(softplusf(d[3]), rsB, -nxb1);
                    loss = fmaf(t2, t2, loss);
                    loss = fmaf(t3, t3, loss);
                }
            }
        }
    }

    // deterministic CTA reduction
    float* sRed = (float*)(dsm + RED);
    __syncthreads();
    sRed[tid] = loss;
    __syncthreads();
#pragma unroll
    for (int o = 128; o; o >>= 1) {
        if (tid < o) sRed[tid] += sRed[tid + o];
        __syncthreads();
    }
    if (tid == 0) g_partials[blockIdx.x] = sRed[0];
}

// ---------------- finalize ----------------
__global__ void finalize_kernel(float* __restrict__ out) {
    __shared__ double red[256];
    const int tid = threadIdx.x;

    double s = 0.0;
    for (int k = tid; k < GRID; k += 256) s += (double)g_partials[k];
    red[tid] = s;
    __syncthreads();
    for (int o = 128; o; o >>= 1) {
        if (tid < o) red[tid] += red[tid + o];
        __syncthreads();
    }
    if (tid == 0)
        out[0] = (float)(red[0] / ((double)(S_LEN - 1) * (double)NDIM));
    __syncthreads();

    double l1 = 0.0;
    for (int k = tid; k < NDIM * NDIM; k += 256) {
        const float w = g_W[k];
        l1 += (double)(1.0f / (1.0f + __expf(-w)));
    }
    red[tid] = l1;
    __syncthreads();
    for (int o = 128; o; o >>= 1) {
        if (tid < o) red[tid] += red[tid + o];
        __syncthreads();
    }
    if (tid == 0) out[1] = (float)red[0];
}

// ---------------- launch ----------------
extern "C" void kernel_launch(void* const* d_in, const int* in_sizes, int n_in,
                              void* d_out, int out_size) {
    const float* In = (const float*)d_in[0];
    const float* WQ = (const float*)d_in[1];
    const float* WK = (const float*)d_in[2];
    float* out = (float*)d_out;

    const int wq_smem = (NDIM * NDIM + NDIM * 8) * sizeof(float);
    cudaFuncSetAttribute(compute_W_kernel,
                         cudaFuncAttributeMaxDynamicSharedMemorySize, wq_smem);
    compute_W_kernel<<<16, 256, wq_smem>>>(WQ, WK);

    cudaFuncSetAttribute(fused_kernel,
                         cudaFuncAttributeMaxDynamicSharedMemorySize, SMEM_BYTES);
    fused_kernel<<<GRID, 256, SMEM_BYTES>>>(In);

    finalize_kernel<<<1, 256>>>(out);
}

// round 7
// speedup vs baseline: 1.2770x; 1.2770x over previous
#include <cuda_runtime.h>
#include <cuda_bf16.h>
#include <cstdint>

#define S_LEN  262144
#define NDIM   128
#define TILE   128
#define NTILES 2048
#define NCTA   296        // 2 CTAs per SM x 148 SMs

// ---------------- device scratch ----------------
__device__ float g_W[NDIM * NDIM];                          // M (fp32, for l1)
__device__ __align__(16) __nv_bfloat16 g_Bsw[NDIM * NDIM];  // B[t][k]=bf16(M[k][t]), swizzled
__device__ float g_partials[NCTA];

// ---------------- smem byte offsets (per CTA: 99840 B -> 2 CTAs/SM) ----------------
#define STG   0          // fp32 staging: 128 x 512B = 65536 (single buffer)
#define BOF   65536      // B bf16 swizzled: 32768
#define NXT   98304      // boundary row fp32: 512
#define RED   98816      // reduction: 256 fp32 = 1024
#define SMEM_BYTES 99840

// ---------------- helpers ----------------
__device__ __forceinline__ uint32_t smem_u32(const void* p) {
    uint32_t a;
    asm("{ .reg .u64 t; cvta.to.shared.u64 t, %1; cvt.u32.u64 %0, t; }" : "=r"(a) : "l"(p));
    return a;
}
__device__ __forceinline__ uint32_t bf2(float xh, float xl) {
    uint32_t r;
    asm("cvt.rn.bf16x2.f32 %0, %1, %2;" : "=r"(r) : "f"(xh), "f"(xl));
    return r;
}
__device__ __forceinline__ float4 lds128f(uint32_t a) {
    float4 v;
    asm volatile("ld.shared.v4.f32 {%0,%1,%2,%3}, [%4];"
                 : "=f"(v.x), "=f"(v.y), "=f"(v.z), "=f"(v.w) : "r"(a));
    return v;
}
__device__ __forceinline__ float2 lds64f(uint32_t a) {
    float2 v;
    asm volatile("ld.shared.v2.f32 {%0,%1}, [%2];" : "=f"(v.x), "=f"(v.y) : "r"(a));
    return v;
}
__device__ __forceinline__ uint2 lds64u(uint32_t a) {
    uint2 v;
    asm volatile("ld.shared.v2.b32 {%0,%1}, [%2];" : "=r"(v.x), "=r"(v.y) : "r"(a));
    return v;
}
__device__ __forceinline__ void cpa16(uint32_t dst, const void* src) {
    asm volatile("cp.async.cg.shared.global [%0], [%1], 16;" :: "r"(dst), "l"(src));
}
__device__ __forceinline__ void cpa_commit() { asm volatile("cp.async.commit_group;" ::: "memory"); }
__device__ __forceinline__ void cpa_wait0()  { asm volatile("cp.async.wait_group 0;" ::: "memory"); }

__device__ __forceinline__ void mma_bf16(float* d, const uint32_t* a, uint32_t b0, uint32_t b1) {
    asm volatile(
        "mma.sync.aligned.m16n8k16.row.col.f32.bf16.bf16.f32 "
        "{%0,%1,%2,%3}, {%4,%5,%6,%7}, {%8,%9}, {%0,%1,%2,%3};"
        : "+f"(d[0]), "+f"(d[1]), "+f"(d[2]), "+f"(d[3])
        : "r"(a[0]), "r"(a[1]), "r"(a[2]), "r"(a[3]), "r"(b0), "r"(b1));
}
__device__ __forceinline__ float softplusf(float x) {
    const float l = __logf(1.0f + __expf(x));
    return (x > 15.0f) ? x : l;
}
// swizzled byte offset: col t, k index (B plane, 256B rows)
__device__ __forceinline__ uint32_t bswz(int t, int k) {
    return (uint32_t)(t * 256 + (((k >> 2) ^ ((t & 7) << 2)) << 3) + (k & 3) * 2);
}

// ---------------- kernel A: M = W_K^T @ W_Q (64 blocks, WQ from L2) ----------------
__global__ void __launch_bounds__(256, 1)
compute_W_kernel(const float* __restrict__ WQ, const float* __restrict__ WK) {
    __shared__ float sWK[256];           // columns i0, i0+1 interleaved: sWK[2j+u]
    const int tid = threadIdx.x;
    const int i0  = blockIdx.x * 2;
    {
        const int j = tid >> 1, u = tid & 1;
        sWK[tid] = WK[j * NDIM + i0 + u];
    }
    __syncthreads();
    const int t = tid & 127;
    const int u = tid >> 7;
    float acc = 0.f;
#pragma unroll 8
    for (int j = 0; j < NDIM; ++j)
        acc = fmaf(sWK[2 * j + u], __ldg(WQ + j * NDIM + t), acc);
    const int i = i0 + u;                        // k index of B
    g_W[i * NDIM + t] = acc;
    *(__nv_bfloat16*)((char*)g_Bsw + bswz(t, i)) = __float2bfloat16(acc);
}

// ---------------- fused persistent kernel ----------------
extern __shared__ char dsm[];

__device__ __forceinline__ void issue_prefetch(const float* __restrict__ In, int tile,
                                               uint32_t sb, int tid) {
    const char* src = (const char*)(In + (size_t)tile * TILE * NDIM);
#pragma unroll
    for (int j = 0; j < 16; ++j) {
        const int idx = tid + 256 * j;           // 4096 16B chunks
        const int r = idx >> 5, c = idx & 31;
        cpa16(sb + STG + r * 512 + ((c ^ ((r & 1) << 2)) << 4), src + r * 512 + c * 16);
    }
    if (tid < 32) {
        size_t nr = (size_t)tile * TILE + TILE;
        if (nr >= S_LEN) nr = 0;                  // clamped; value masked out
        cpa16(sb + NXT + tid * 16, (const char*)(In + nr * NDIM) + tid * 16);
    }
    cpa_commit();
}

__global__ void __launch_bounds__(256, 2)
fused_kernel(const float* __restrict__ In) {
    const uint32_t sb = smem_u32(dsm);
    const int tid  = threadIdx.x;
    const int lane = tid & 31;
    const int w    = tid >> 5;
    const int m0   = (w & 3) << 5;     // warp tile: 32m x 64n (grid 4m x 2n)
    const int n0   = (w >> 2) << 6;
    const int g    = lane >> 2;
    const int q    = lane & 3;

    // stage B (global already swizzled) -> smem
    {
        const float4* src = (const float4*)g_Bsw;
        float4* dst = (float4*)(dsm + BOF);
#pragma unroll
        for (int k = tid; k < 2048; k += 256) dst[k] = src[k];
    }

    const int rA0 = m0 + g;
    const uint32_t xA = (uint32_t)((g & 1) << 2);
    const uint32_t xB = (uint32_t)(g << 2);
    const uint32_t bA = sb + STG + (uint32_t)rA0 * 512;
    const uint32_t bB = sb + BOF + (uint32_t)(n0 + g) * 256;

    const int bx = blockIdx.x;
    const int nt = (NTILES - bx + NCTA - 1) / NCTA;

    issue_prefetch(In, bx, sb, tid);

    float loss = 0.f;
    for (int i = 0; i < nt; ++i) {
        const int tile = bx + i * NCTA;
        cpa_wait0();
        __syncthreads();                 // staging ready

        float dacc[2][8][4];
#pragma unroll
        for (int mh = 0; mh < 2; ++mh)
#pragma unroll
            for (int nf = 0; nf < 8; ++nf)
#pragma unroll
                for (int j = 0; j < 4; ++j) dacc[mh][nf][j] = 0.f;
        float rsum[4] = {0.f, 0.f, 0.f, 0.f};

#pragma unroll
        for (int ks = 0; ks < 8; ++ks) {
            const uint32_t c = (uint32_t)(4 * ks + q);
            const uint32_t offA = ((c ^ xA) << 4);
            const float4 v00 = lds128f(bA + offA);               // row rA0
            const float4 v01 = lds128f(bA + 8 * 512 + offA);     // row rA0+8
            const float4 v10 = lds128f(bA + 16 * 512 + offA);    // row rA0+16
            const float4 v11 = lds128f(bA + 24 * 512 + offA);    // row rA0+24
            rsum[0] += (v00.x + v00.y) + (v00.z + v00.w);
            rsum[1] += (v01.x + v01.y) + (v01.z + v01.w);
            rsum[2] += (v10.x + v10.y) + (v10.z + v10.w);
            rsum[3] += (v11.x + v11.y) + (v11.z + v11.w);
            uint32_t a0[4], a1[4];
            a0[0] = bf2(v00.y, v00.x); a0[1] = bf2(v01.y, v01.x);
            a0[2] = bf2(v00.w, v00.z); a0[3] = bf2(v01.w, v01.z);
            a1[0] = bf2(v10.y, v10.x); a1[1] = bf2(v11.y, v11.x);
            a1[2] = bf2(v10.w, v10.z); a1[3] = bf2(v11.w, v11.z);
            const uint32_t offB = ((c ^ xB) << 3);
#pragma unroll
            for (int nf = 0; nf < 8; ++nf) {
                const uint2 b = lds64u(bB + (uint32_t)nf * 2048 + offB);
                mma_bf16(dacc[0][nf], a0, b.x, b.y);
                mma_bf16(dacc[1][nf], a1, b.x, b.y);
            }
        }

        // quad-reduce rowsums
#pragma unroll
        for (int j = 0; j < 4; ++j) {
            rsum[j] += __shfl_xor_sync(0xffffffffu, rsum[j], 1);
            rsum[j] += __shfl_xor_sync(0xffffffffu, rsum[j], 2);
        }

        // -------- epilogue --------
        const size_t base = (size_t)tile * TILE;
        const uint32_t xN = (uint32_t)(((g + 1) & 1) << 2);     // row parity of rA+1
#pragma unroll
        for (int mh = 0; mh < 2; ++mh) {
            const int rA = m0 + 16 * mh + g;        // <= 119 (always valid)
            const int rB = rA + 8;                  // <= 127
            const float rsA = rsum[2 * mh];
            const float rsB = rsum[2 * mh + 1];
            const bool vB = (base + rB) < (size_t)(S_LEN - 1);
#pragma unroll
            for (int nf = 0; nf < 8; ++nf) {
                const int col0 = n0 + 8 * nf + 2 * q;
                const uint32_t off = (((uint32_t)(col0 >> 2) ^ xN) << 4) + ((col0 & 3) << 2);
                const float2 nxa = lds64f(sb + STG + (uint32_t)(rA + 1) * 512 + off);
                const float2 nxb = (rB < TILE - 1)
                                       ? lds64f(sb + STG + (uint32_t)(rB + 1) * 512 + off)
                                       : lds64f(sb + NXT + col0 * 4);
                const float* d = dacc[mh][nf];
                const float t0 = fmaf(softplusf(d[0]), rsA, -nxa.x);
                const float t1 = fmaf(softplusf(d[1]), rsA, -nxa.y);
                loss = fmaf(t0, t0, loss);
                loss = fmaf(t1, t1, loss);
                if (vB) {
                    const float t2 = fmaf(softplusf(d[2]), rsB, -nxb.x);
                    const float t3 = fmaf(softplusf(d[3]), rsB, -nxb.y);
                    loss = fmaf(t2, t2, loss);
                    loss = fmaf(t3, t3, loss);
                }
            }
        }

        __syncthreads();                 // all warps done reading staging
        if (i + 1 < nt) issue_prefetch(In, bx + (i + 1) * NCTA, sb, tid);
    }

    // deterministic CTA reduction
    float* sRed = (float*)(dsm + RED);
    sRed[tid] = loss;
    __syncthreads();
#pragma unroll
    for (int o = 128; o; o >>= 1) {
        if (tid < o) sRed[tid] += sRed[tid + o];
        __syncthreads();
    }
    if (tid == 0) g_partials[blockIdx.x] = sRed[0];
}

// ---------------- finalize ----------------
__global__ void finalize_kernel(float* __restrict__ out) {
    __shared__ double red[256];
    const int tid = threadIdx.x;

    double s = 0.0;
    for (int k = tid; k < NCTA; k += 256) s += (double)g_partials[k];
    red[tid] = s;
    __syncthreads();
    for (int o = 128; o; o >>= 1) {
        if (tid < o) red[tid] += red[tid + o];
        __syncthreads();
    }
    if (tid == 0)
        out[0] = (float)(red[0] / ((double)(S_LEN - 1) * (double)NDIM));
    __syncthreads();

    double l1 = 0.0;
    for (int k = tid; k < NDIM * NDIM; k += 256) {
        const float w = g_W[k];
        l1 += (double)(1.0f / (1.0f + __expf(-w)));
    }
    red[tid] = l1;
    __syncthreads();
    for (int o = 128; o; o >>= 1) {
        if (tid < o) red[tid] += red[tid + o];
        __syncthreads();
    }
    if (tid == 0) out[1] = (float)red[0];
}

// ---------------- launch ----------------
extern "C" void kernel_launch(void* const* d_in, const int* in_sizes, int n_in,
                              void* d_out, int out_size) {
    const float* In = (const float*)d_in[0];
    const float* WQ = (const float*)d_in[1];
    const float* WK = (const float*)d_in[2];
    float* out = (float*)d_out;

    compute_W_kernel<<<64, 256>>>(WQ, WK);

    cudaFuncSetAttribute(fused_kernel,
                         cudaFuncAttributeMaxDynamicSharedMemorySize, SMEM_BYTES);
    fused_kernel<<<NCTA, 256, SMEM_BYTES>>>(In);

    finalize_kernel<<<1, 256>>>(out);
}